// round 3
// baseline (speedup 1.0000x reference)
#include <cuda_runtime.h>

#define SEQ   2048
#define EMB   1024
#define NH    16
#define HSZ   64
#define BATCH 2
#define ROWS  (BATCH * SEQ)     // 4096
#define D3    (3 * EMB)         // 3072

// Scratch (device globals — no allocation allowed)
__device__ float g_qkv[ROWS * D3];     // [b*s, 3*EMB]  (q | k | v per row)
__device__ float g_obuf[ROWS * EMB];   // attention output, [b*s, EMB]

// ---------------------------------------------------------------------------
// SGEMM + bias:  C[M,N] = A[M,K] @ B[K,N] + bias[N]
// MODE 0: A = param (x),      C = g_qkv
// MODE 1: A = g_obuf,         C = param (out)
// 128x128 tile, BK=8, 256 threads, 8x8 per thread.
// M % 128 == 0, N % 128 == 0, K % 8 == 0 (all true here).
// ---------------------------------------------------------------------------
template <int MODE>
__global__ __launch_bounds__(256)
void sgemm_bias(const float* __restrict__ Ain,
                const float* __restrict__ B,
                const float* __restrict__ bias,
                float* __restrict__ Cout,
                int M, int N, int K)
{
    const float* A = (MODE == 0) ? Ain : g_obuf;
    float* C       = (MODE == 0) ? g_qkv : Cout;

    __shared__ float As[8][128];   // As[k][m]
    __shared__ float Bs[8][128];   // Bs[k][n]

    const int tid = threadIdx.x;
    const int bx = blockIdx.x, by = blockIdx.y;

    // A tile load mapping: 128x8 floats = 256 float4
    const int a_row = tid >> 1;          // 0..127
    const int a_col = (tid & 1) * 4;     // 0 or 4
    // B tile load mapping: 8x128 floats = 256 float4
    const int b_row = tid >> 5;          // 0..7
    const int b_col = (tid & 31) * 4;

    const int tx = tid & 15;             // 0..15 (cols)
    const int ty = tid >> 4;             // 0..15 (rows)

    const float* Ab = A + (long)(by * 128) * K;
    const float* Bb = B + bx * 128;

    float acc[8][8];
#pragma unroll
    for (int i = 0; i < 8; i++)
#pragma unroll
        for (int j = 0; j < 8; j++) acc[i][j] = 0.f;

    for (int k0 = 0; k0 < K; k0 += 8) {
        float4 av = *(const float4*)(Ab + (long)a_row * K + k0 + a_col);
        float4 bv = *(const float4*)(Bb + (long)(k0 + b_row) * N + b_col);

        As[a_col + 0][a_row] = av.x;
        As[a_col + 1][a_row] = av.y;
        As[a_col + 2][a_row] = av.z;
        As[a_col + 3][a_row] = av.w;
        *(float4*)&Bs[b_row][b_col] = bv;
        __syncthreads();

#pragma unroll
        for (int k = 0; k < 8; k++) {
            float ra[8], rb[8];
            *(float4*)&ra[0] = *(const float4*)&As[k][ty * 8];
            *(float4*)&ra[4] = *(const float4*)&As[k][ty * 8 + 4];
            *(float4*)&rb[0] = *(const float4*)&Bs[k][tx * 8];
            *(float4*)&rb[4] = *(const float4*)&Bs[k][tx * 8 + 4];
#pragma unroll
            for (int i = 0; i < 8; i++)
#pragma unroll
                for (int j = 0; j < 8; j++)
                    acc[i][j] += ra[i] * rb[j];
        }
        __syncthreads();
    }

    // epilogue + bias
#pragma unroll
    for (int i = 0; i < 8; i++) {
        const int row = by * 128 + ty * 8 + i;
#pragma unroll
        for (int j = 0; j < 8; j += 4) {
            const int col = bx * 128 + tx * 8 + j;
            float4 c;
            c.x = acc[i][j + 0] + bias[col + 0];
            c.y = acc[i][j + 1] + bias[col + 1];
            c.z = acc[i][j + 2] + bias[col + 2];
            c.w = acc[i][j + 3] + bias[col + 3];
            *(float4*)&C[(long)row * N + col] = c;
        }
    }
}

// ---------------------------------------------------------------------------
// Flash-attention fp32, causal. 64-row Q tile, 64-col K/V tiles, hs=64.
// Block = 256 threads; thread t: row r = t/4, lane-group cg = t%4.
// Each thread owns 16 score columns (interleaved c = cg + 4j for bank spread)
// and 16 output dims (d = cg*16 + j).
// smem: Q,K,V,P tiles with pitch 68 (row shift of 4 banks -> conflict-free).
// ---------------------------------------------------------------------------
#define PITCH 68
#define SMEM_ATTN (4 * 64 * PITCH * 4)

__global__ __launch_bounds__(256, 2)
void attn_kernel()
{
    extern __shared__ float sm[];
    float* Qs = sm;
    float* Ks = Qs + 64 * PITCH;
    float* Vs = Ks + 64 * PITCH;
    float* Ps = Vs + 64 * PITCH;

    const int qt = blockIdx.x;          // q tile (0..31)
    const int h  = blockIdx.y;          // head
    const int b  = blockIdx.z;          // batch
    const int tid = threadIdx.x;
    const int r  = tid >> 2;            // q row in tile, 0..63
    const int cg = tid & 3;             // column group, 0..3

    const float* base = g_qkv + (long)b * SEQ * D3 + h * HSZ;
    const float* qp = base;             // +0    -> Q
    const float* kp = base + EMB;       // +1024 -> K
    const float* vp = base + 2 * EMB;   // +2048 -> V

    const int q0 = qt * 64;
    const int qg = q0 + r;

    // load Q tile
#pragma unroll
    for (int idx = tid; idx < 64 * 64; idx += 256) {
        int s = idx >> 6, d = idx & 63;
        Qs[s * PITCH + d] = qp[(long)(q0 + s) * D3 + d];
    }

    float m = -1e30f, l = 0.f;
    float acc[16];
#pragma unroll
    for (int j = 0; j < 16; j++) acc[j] = 0.f;

    for (int kt = 0; kt <= qt; kt++) {
        __syncthreads();   // prev PV done (and Q load on first iter)
        // load K,V tiles
        const int k0 = kt * 64;
#pragma unroll
        for (int idx = tid; idx < 64 * 64; idx += 256) {
            int s = idx >> 6, d = idx & 63;
            Ks[s * PITCH + d] = kp[(long)(k0 + s) * D3 + d];
            Vs[s * PITCH + d] = vp[(long)(k0 + s) * D3 + d];
        }
        __syncthreads();

        // scores: sc[j] = Q[r,:] . K[cg+4j,:]   (interleaved columns)
        float sc[16];
#pragma unroll
        for (int j = 0; j < 16; j++) sc[j] = 0.f;
        const float* qrow = Qs + r * PITCH;
#pragma unroll
        for (int i = 0; i < 64; i += 4) {
            float4 q4 = *(const float4*)(qrow + i);
#pragma unroll
            for (int j = 0; j < 16; j++) {
                float4 k4 = *(const float4*)(Ks + (cg + 4 * j) * PITCH + i);
                sc[j] += q4.x * k4.x + q4.y * k4.y + q4.z * k4.z + q4.w * k4.w;
            }
        }

        // scale + causal mask
        float tmax = -1e30f;
#pragma unroll
        for (int j = 0; j < 16; j++) {
            sc[j] *= 0.125f;                       // 1/sqrt(64)
            int kg = k0 + cg + 4 * j;
            if (kt == qt && kg > qg) sc[j] = -1e30f;
            tmax = fmaxf(tmax, sc[j]);
        }
        // row max across the 4-lane group (lanes 4r..4r+3, same warp)
        tmax = fmaxf(tmax, __shfl_xor_sync(0xffffffffu, tmax, 1));
        tmax = fmaxf(tmax, __shfl_xor_sync(0xffffffffu, tmax, 2));
        float mnew = fmaxf(m, tmax);

        float psum = 0.f;
        float* prow = Ps + r * PITCH;
#pragma unroll
        for (int j = 0; j < 16; j++) {
            float p = __expf(sc[j] - mnew);
            psum += p;
            prow[cg + 4 * j] = p;
        }
        psum += __shfl_xor_sync(0xffffffffu, psum, 1);
        psum += __shfl_xor_sync(0xffffffffu, psum, 2);

        float scale = __expf(m - mnew);
        l = l * scale + psum;
        m = mnew;
#pragma unroll
        for (int j = 0; j < 16; j++) acc[j] *= scale;

        __syncwarp();   // P row written by 4 lanes of this warp

        // PV: acc[d] += sum_k P[r,k] * V[k, d],  d = cg*16 + (0..15)
        const float* vbase = Vs + cg * 16;
#pragma unroll 8
        for (int k = 0; k < 64; k++) {
            float p = prow[k];
            const float* vrow = vbase + k * PITCH;
            float4 v0 = *(const float4*)(vrow + 0);
            float4 v1 = *(const float4*)(vrow + 4);
            float4 v2 = *(const float4*)(vrow + 8);
            float4 v3 = *(const float4*)(vrow + 12);
            acc[0]  += p * v0.x;  acc[1]  += p * v0.y;
            acc[2]  += p * v0.z;  acc[3]  += p * v0.w;
            acc[4]  += p * v1.x;  acc[5]  += p * v1.y;
            acc[6]  += p * v1.z;  acc[7]  += p * v1.w;
            acc[8]  += p * v2.x;  acc[9]  += p * v2.y;
            acc[10] += p * v2.z;  acc[11] += p * v2.w;
            acc[12] += p * v3.x;  acc[13] += p * v3.y;
            acc[14] += p * v3.z;  acc[15] += p * v3.w;
        }
    }

    // finalize: O[b, qg, h*64 + d] = acc/l
    const float inv = 1.f / l;
    float* orow = g_obuf + (long)(b * SEQ + qg) * EMB + h * HSZ + cg * 16;
#pragma unroll
    for (int j = 0; j < 16; j += 4) {
        float4 o;
        o.x = acc[j + 0] * inv;
        o.y = acc[j + 1] * inv;
        o.z = acc[j + 2] * inv;
        o.w = acc[j + 3] * inv;
        *(float4*)&orow[j] = o;
    }
}

// ---------------------------------------------------------------------------
extern "C" void kernel_launch(void* const* d_in, const int* in_sizes, int n_in,
                              void* d_out, int out_size)
{
    const float* x     = (const float*)d_in[0];
    const float* W_qkv = (const float*)d_in[1];
    const float* b_qkv = (const float*)d_in[2];
    const float* W_out = (const float*)d_in[3];
    const float* b_out = (const float*)d_in[4];
    float* out = (float*)d_out;

    // 1) QKV projection: g_qkv = x @ W_qkv + b_qkv
    sgemm_bias<0><<<dim3(D3 / 128, ROWS / 128), 256>>>(
        x, W_qkv, b_qkv, nullptr, ROWS, D3, EMB);

    // 2) causal flash attention -> g_obuf
    cudaFuncSetAttribute(attn_kernel,
                         cudaFuncAttributeMaxDynamicSharedMemorySize, SMEM_ATTN);
    attn_kernel<<<dim3(SEQ / 64, NH, BATCH), 256, SMEM_ATTN>>>();

    // 3) output projection: out = g_obuf @ W_out + b_out
    sgemm_bias<1><<<dim3(EMB / 128, ROWS / 128), 256>>>(
        nullptr, W_out, b_out, out, ROWS, EMB, EMB);
}

// round 4
// speedup vs baseline: 1.7960x; 1.7960x over previous
#include <cuda_runtime.h>

#define SEQ   2048
#define EMB   1024
#define NH    16
#define HSZ   64
#define BATCH 2
#define ROWS  (BATCH * SEQ)     // 4096
#define D3    (3 * EMB)         // 3072

// Scratch (device globals — no allocation allowed)
__device__ float g_qkv[ROWS * D3];     // [b*s, 3*EMB]  (q | k | v per row)
__device__ float g_obuf[ROWS * EMB];   // attention output, [b*s, EMB]

// ---------------------------------------------------------------------------
// SGEMM + bias:  C[M,N] = A[M,K] @ B[K,N] + bias[N]
// 128x128 tile, BK=8, 256 threads, 8x8 per thread, double-buffered smem.
// ---------------------------------------------------------------------------
template <int MODE>
__global__ __launch_bounds__(256)
void sgemm_bias(const float* __restrict__ Ain,
                const float* __restrict__ B,
                const float* __restrict__ bias,
                float* __restrict__ Cout,
                int M, int N, int K)
{
    const float* A = (MODE == 0) ? Ain : g_obuf;
    float* C       = (MODE == 0) ? g_qkv : Cout;

    __shared__ float As[2][8][128];   // As[buf][k][m]
    __shared__ float Bs[2][8][128];   // Bs[buf][k][n]

    const int tid = threadIdx.x;
    const int bx = blockIdx.x, by = blockIdx.y;

    const int a_row = tid >> 1;          // 0..127
    const int a_col = (tid & 1) * 4;     // 0 or 4
    const int b_row = tid >> 5;          // 0..7
    const int b_col = (tid & 31) * 4;

    const int tx = tid & 15;             // 0..15 (cols)
    const int ty = tid >> 4;             // 0..15 (rows)

    const float* Ab = A + (long)(by * 128) * K;
    const float* Bb = B + bx * 128;

    float acc[8][8];
#pragma unroll
    for (int i = 0; i < 8; i++)
#pragma unroll
        for (int j = 0; j < 8; j++) acc[i][j] = 0.f;

    // preload first tile
    {
        float4 av = *(const float4*)(Ab + (long)a_row * K + a_col);
        float4 bv = *(const float4*)(Bb + (long)b_row * N + b_col);
        As[0][a_col + 0][a_row] = av.x;
        As[0][a_col + 1][a_row] = av.y;
        As[0][a_col + 2][a_row] = av.z;
        As[0][a_col + 3][a_row] = av.w;
        *(float4*)&Bs[0][b_row][b_col] = bv;
    }
    __syncthreads();

    int buf = 0;
    for (int k0 = 0; k0 < K; k0 += 8) {
        const bool more = (k0 + 8 < K);
        float4 av2, bv2;
        if (more) {
            av2 = *(const float4*)(Ab + (long)a_row * K + (k0 + 8) + a_col);
            bv2 = *(const float4*)(Bb + (long)(k0 + 8 + b_row) * N + b_col);
        }

#pragma unroll
        for (int k = 0; k < 8; k++) {
            float ra[8], rb[8];
            *(float4*)&ra[0] = *(const float4*)&As[buf][k][ty * 8];
            *(float4*)&ra[4] = *(const float4*)&As[buf][k][ty * 8 + 4];
            *(float4*)&rb[0] = *(const float4*)&Bs[buf][k][tx * 8];
            *(float4*)&rb[4] = *(const float4*)&Bs[buf][k][tx * 8 + 4];
#pragma unroll
            for (int i = 0; i < 8; i++)
#pragma unroll
                for (int j = 0; j < 8; j++)
                    acc[i][j] += ra[i] * rb[j];
        }

        if (more) {
            As[buf ^ 1][a_col + 0][a_row] = av2.x;
            As[buf ^ 1][a_col + 1][a_row] = av2.y;
            As[buf ^ 1][a_col + 2][a_row] = av2.z;
            As[buf ^ 1][a_col + 3][a_row] = av2.w;
            *(float4*)&Bs[buf ^ 1][b_row][b_col] = bv2;
            __syncthreads();
            buf ^= 1;
        }
    }

    // epilogue + bias
#pragma unroll
    for (int i = 0; i < 8; i++) {
        const int row = by * 128 + ty * 8 + i;
#pragma unroll
        for (int j = 0; j < 8; j += 4) {
            const int col = bx * 128 + tx * 8 + j;
            float4 c;
            c.x = acc[i][j + 0] + bias[col + 0];
            c.y = acc[i][j + 1] + bias[col + 1];
            c.z = acc[i][j + 2] + bias[col + 2];
            c.w = acc[i][j + 3] + bias[col + 3];
            *(float4*)&C[(long)row * N + col] = c;
        }
    }
}

// ---------------------------------------------------------------------------
// Flash-attention fp32, causal. Register-blocked 4x4 per thread.
// Q tile 64 rows x K tile 64 cols, hs=64, 256 threads (16x16 thread grid).
// Thread (ty,tx): score rows ty*4..+3, score cols / out dims tx*4..+3.
// QKt and PV are both outer-product GEMMs: 2 LDS.128 per 16 FMA.
// smem tiles (pitch 68, fp32):
//   QT[d][i]  = Q[q0+i][d]   (transposed)
//   KT[d][j]  = K[k0+j][d]   (transposed)
//   Vs[k][d]  = V[k0+k][d]
//   PT[k][i]  = P[i][k]      (transposed, written after softmax)
// ---------------------------------------------------------------------------
#define PITCH 68
#define SMEM_ATTN (4 * 64 * PITCH * 4)

__global__ __launch_bounds__(256, 2)
void attn_kernel()
{
    extern __shared__ float sm[];
    float* QT = sm;
    float* KT = QT + 64 * PITCH;
    float* Vs = KT + 64 * PITCH;
    float* PT = Vs + 64 * PITCH;

    const int qt = gridDim.x - 1 - blockIdx.x;   // long blocks first
    const int h  = blockIdx.y;
    const int b  = blockIdx.z;
    const int tid = threadIdx.x;
    const int tx = tid & 15;             // 0..15
    const int ty = tid >> 4;             // 0..15

    const float* base = g_qkv + (long)b * SEQ * D3 + h * HSZ;
    const float* qp = base;             // Q
    const float* kp = base + EMB;       // K  (V = K + EMB)

    const int q0 = qt * 64;

    // load Q tile transposed: QT[d][i] = Q[q0+i][d]
#pragma unroll
    for (int idx = tid; idx < 1024; idx += 256) {
        int s  = idx >> 4;
        int d4 = (idx & 15) << 2;
        float4 q = *(const float4*)(qp + (long)(q0 + s) * D3 + d4);
        QT[(d4 + 0) * PITCH + s] = q.x;
        QT[(d4 + 1) * PITCH + s] = q.y;
        QT[(d4 + 2) * PITCH + s] = q.z;
        QT[(d4 + 3) * PITCH + s] = q.w;
    }

    float m[4], l[4], acc[4][4];
#pragma unroll
    for (int i = 0; i < 4; i++) {
        m[i] = -1e30f; l[i] = 0.f;
#pragma unroll
        for (int j = 0; j < 4; j++) acc[i][j] = 0.f;
    }

    for (int kt = 0; kt <= qt; kt++) {
        __syncthreads();   // prev PV done (iter0: barrier before K/V overwrite ok)
        const int k0 = kt * 64;
        // load K transposed + V natural
#pragma unroll
        for (int idx = tid; idx < 1024; idx += 256) {
            int s  = idx >> 4;
            int d4 = (idx & 15) << 2;
            const float* krow = kp + (long)(k0 + s) * D3 + d4;
            float4 kk = *(const float4*)krow;
            float4 vv = *(const float4*)(krow + EMB);
            KT[(d4 + 0) * PITCH + s] = kk.x;
            KT[(d4 + 1) * PITCH + s] = kk.y;
            KT[(d4 + 2) * PITCH + s] = kk.z;
            KT[(d4 + 3) * PITCH + s] = kk.w;
            *(float4*)&Vs[s * PITCH + d4] = vv;
        }
        __syncthreads();

        // ---- QK^T: sc[ii][jj] = Q[ty4+ii,:] . K[tx4+jj,:] ----
        float sc[4][4];
#pragma unroll
        for (int i = 0; i < 4; i++)
#pragma unroll
            for (int j = 0; j < 4; j++) sc[i][j] = 0.f;

#pragma unroll 4
        for (int d = 0; d < 64; d++) {
            float4 a = *(const float4*)&QT[d * PITCH + ty * 4];
            float4 bq = *(const float4*)&KT[d * PITCH + tx * 4];
            float ra[4] = {a.x, a.y, a.z, a.w};
            float rb[4] = {bq.x, bq.y, bq.z, bq.w};
#pragma unroll
            for (int i = 0; i < 4; i++)
#pragma unroll
                for (int j = 0; j < 4; j++)
                    sc[i][j] += ra[i] * rb[j];
        }

        // ---- scale + causal mask + row max ----
        float rowm[4];
#pragma unroll
        for (int i = 0; i < 4; i++) {
            rowm[i] = -1e30f;
#pragma unroll
            for (int j = 0; j < 4; j++) {
                float v = sc[i][j] * 0.125f;      // 1/sqrt(64)
                if (kt == qt && (tx * 4 + j) > (ty * 4 + i)) v = -1e30f;
                sc[i][j] = v;
                rowm[i] = fmaxf(rowm[i], v);
            }
        }
        // reduce max across the 16 lanes sharing the same rows
#pragma unroll
        for (int ofs = 1; ofs < 16; ofs <<= 1)
#pragma unroll
            for (int i = 0; i < 4; i++)
                rowm[i] = fmaxf(rowm[i], __shfl_xor_sync(0xffffffffu, rowm[i], ofs));

        float esc[4], psum[4];
#pragma unroll
        for (int i = 0; i < 4; i++) {
            float mnew = fmaxf(m[i], rowm[i]);
            esc[i] = __expf(m[i] - mnew);
            m[i] = mnew;
            psum[i] = 0.f;
#pragma unroll
            for (int j = 0; j < 4; j++) {
                float p = __expf(sc[i][j] - mnew);
                psum[i] += p;
                PT[(tx * 4 + j) * PITCH + ty * 4 + i] = p;   // transposed
            }
        }
#pragma unroll
        for (int ofs = 1; ofs < 16; ofs <<= 1)
#pragma unroll
            for (int i = 0; i < 4; i++)
                psum[i] += __shfl_xor_sync(0xffffffffu, psum[i], ofs);

#pragma unroll
        for (int i = 0; i < 4; i++) {
            l[i] = l[i] * esc[i] + psum[i];
#pragma unroll
            for (int j = 0; j < 4; j++) acc[i][j] *= esc[i];
        }

        __syncthreads();   // PT fully written

        // ---- PV: acc[ii][dd] += sum_k P[ty4+ii][k] * V[k][tx4+dd] ----
#pragma unroll 4
        for (int k = 0; k < 64; k++) {
            float4 a = *(const float4*)&PT[k * PITCH + ty * 4];
            float4 bv = *(const float4*)&Vs[k * PITCH + tx * 4];
            float ra[4] = {a.x, a.y, a.z, a.w};
            float rb[4] = {bv.x, bv.y, bv.z, bv.w};
#pragma unroll
            for (int i = 0; i < 4; i++)
#pragma unroll
                for (int j = 0; j < 4; j++)
                    acc[i][j] += ra[i] * rb[j];
        }
    }

    // ---- finalize: O[b, q0+ty4+ii, h*64 + tx*4 + dd] = acc/l ----
#pragma unroll
    for (int i = 0; i < 4; i++) {
        const float inv = 1.f / l[i];
        const int row = q0 + ty * 4 + i;
        float4 o;
        o.x = acc[i][0] * inv;
        o.y = acc[i][1] * inv;
        o.z = acc[i][2] * inv;
        o.w = acc[i][3] * inv;
        *(float4*)&g_obuf[(long)(b * SEQ + row) * EMB + h * HSZ + tx * 4] = o;
    }
}

// ---------------------------------------------------------------------------
extern "C" void kernel_launch(void* const* d_in, const int* in_sizes, int n_in,
                              void* d_out, int out_size)
{
    const float* x     = (const float*)d_in[0];
    const float* W_qkv = (const float*)d_in[1];
    const float* b_qkv = (const float*)d_in[2];
    const float* W_out = (const float*)d_in[3];
    const float* b_out = (const float*)d_in[4];
    float* out = (float*)d_out;

    // 1) QKV projection: g_qkv = x @ W_qkv + b_qkv
    sgemm_bias<0><<<dim3(D3 / 128, ROWS / 128), 256>>>(
        x, W_qkv, b_qkv, nullptr, ROWS, D3, EMB);

    // 2) causal flash attention -> g_obuf
    cudaFuncSetAttribute(attn_kernel,
                         cudaFuncAttributeMaxDynamicSharedMemorySize, SMEM_ATTN);
    attn_kernel<<<dim3(SEQ / 64, NH, BATCH), 256, SMEM_ATTN>>>();

    // 3) output projection: out = g_obuf @ W_out + b_out
    sgemm_bias<1><<<dim3(EMB / 128, ROWS / 128), 256>>>(
        nullptr, W_out, b_out, out, ROWS, EMB, EMB);
}

// round 6
// speedup vs baseline: 2.6424x; 1.4712x over previous
#include <cuda_runtime.h>
#include <cuda_bf16.h>
#include <cstdint>

#define SEQ   2048
#define EMB   1024
#define NH    16
#define HSZ   64
#define BATCH 2
#define ROWS  (BATCH * SEQ)     // 4096
#define D3    (3 * EMB)         // 3072
#define NCK   (EMB / 32)        // 32 k-stages of BK=32

// Scratch (device globals — no allocation allowed)
__device__ float g_qkv[ROWS * D3];     // [b*s, 3*EMB]
__device__ float g_obuf[ROWS * EMB];   // attention output
__device__ __nv_bfloat16 g_wt1h[D3 * EMB];   // W_qkv^T hi  [3072,1024] (K-major)
__device__ __nv_bfloat16 g_wt1l[D3 * EMB];   // W_qkv^T lo
__device__ __nv_bfloat16 g_wt2h[EMB * EMB];  // W_out^T hi  [1024,1024]
__device__ __nv_bfloat16 g_wt2l[EMB * EMB];  // W_out^T lo
__device__ __nv_bfloat16 g_xh[ROWS * EMB];   // x hi/lo
__device__ __nv_bfloat16 g_xl[ROWS * EMB];
__device__ __nv_bfloat16 g_oh[ROWS * EMB];   // attn-out hi/lo
__device__ __nv_bfloat16 g_ol[ROWS * EMB];

// ============================================================================
// asm helpers (all plain sm_80+ PTX — legal on target sm_103)
// ============================================================================
__device__ __forceinline__ uint32_t smem_to_u32(const void* p) {
    uint32_t a;
    asm("{ .reg .u64 t; cvta.to.shared.u64 t, %1; cvt.u32.u64 %0, t; }"
        : "=r"(a) : "l"(p));
    return a;
}

#define CP_ASYNC16(dst, src) \
    asm volatile("cp.async.cg.shared.global [%0], [%1], 16;" \
                 :: "r"(dst), "l"(__cvta_generic_to_global(src)) : "memory")
#define CP_COMMIT() asm volatile("cp.async.commit_group;" ::: "memory")
#define CP_WAIT0()  asm volatile("cp.async.wait_group 0;" ::: "memory")
#define CP_WAIT1()  asm volatile("cp.async.wait_group 1;" ::: "memory")

#define LDSM_X4(r0, r1, r2, r3, addr) \
    asm volatile("ldmatrix.sync.aligned.m8n8.x4.shared.b16 {%0,%1,%2,%3}, [%4];" \
                 : "=r"(r0), "=r"(r1), "=r"(r2), "=r"(r3) : "r"(addr))

#define MMA_BF16(d, a, b0v, b1v) \
    asm volatile("mma.sync.aligned.m16n8k16.row.col.f32.bf16.bf16.f32 " \
                 "{%0,%1,%2,%3}, {%4,%5,%6,%7}, {%8,%9}, {%0,%1,%2,%3};" \
                 : "+f"((d)[0]), "+f"((d)[1]), "+f"((d)[2]), "+f"((d)[3]) \
                 : "r"((a)[0]), "r"((a)[1]), "r"((a)[2]), "r"((a)[3]), \
                   "r"(b0v), "r"(b1v))

// ============================================================================
// Prep: Wt[n][k] = W[k][n], split into bf16 hi/lo. W is [K, N] row-major.
// ============================================================================
template <int MODE>
__global__ void prep_wt(const float* __restrict__ W, int K, int N)
{
    __nv_bfloat16* Wh = (MODE == 0) ? g_wt1h : g_wt2h;
    __nv_bfloat16* Wl = (MODE == 0) ? g_wt1l : g_wt2l;
    __shared__ float t[32][33];
    const int n0 = blockIdx.x * 32, k0 = blockIdx.y * 32;
    const int tx = threadIdx.x, ty = threadIdx.y;
#pragma unroll
    for (int j = 0; j < 32; j += 8)
        t[ty + j][tx] = W[(long)(k0 + ty + j) * N + n0 + tx];
    __syncthreads();
#pragma unroll
    for (int j = 0; j < 32; j += 8) {
        const int n = n0 + ty + j, k = k0 + tx;
        float v = t[tx][ty + j];
        __nv_bfloat16 h = __float2bfloat16(v);
        Wh[(long)n * K + k] = h;
        Wl[(long)n * K + k] = __float2bfloat16(v - __bfloat162float(h));
    }
}

// ============================================================================
// Prep: split an fp32 activation matrix into bf16 hi/lo (elementwise).
// MODE 0: x -> g_xh/g_xl    MODE 1: g_obuf -> g_oh/g_ol
// ============================================================================
template <int MODE>
__global__ void prep_split(const float* __restrict__ srcp)
{
    const float* s = (MODE == 0) ? srcp : g_obuf;
    __nv_bfloat16* h = (MODE == 0) ? g_xh : g_oh;
    __nv_bfloat16* l = (MODE == 0) ? g_xl : g_ol;
    const int i = blockIdx.x * blockDim.x + threadIdx.x;   // float4 index
    float4 v = ((const float4*)s)[i];
    union { __nv_bfloat16 b[4]; uint2 u; } ph, pl;
    ph.b[0] = __float2bfloat16(v.x);
    ph.b[1] = __float2bfloat16(v.y);
    ph.b[2] = __float2bfloat16(v.z);
    ph.b[3] = __float2bfloat16(v.w);
    pl.b[0] = __float2bfloat16(v.x - __bfloat162float(ph.b[0]));
    pl.b[1] = __float2bfloat16(v.y - __bfloat162float(ph.b[1]));
    pl.b[2] = __float2bfloat16(v.z - __bfloat162float(ph.b[2]));
    pl.b[3] = __float2bfloat16(v.w - __bfloat162float(ph.b[3]));
    ((uint2*)h)[i] = ph.u;
    ((uint2*)l)[i] = pl.u;
}

// ============================================================================
// HMMA GEMM + bias: C[M,N] = (Ahi+Alo)[M,K] @ (Bhi+Blo)^T[N,K] + bias
// 3-MMA split scheme. CTA tile 128x128, BK=32, 256 threads, 8 warps (4m x 2n),
// warp tile 32x64. cp.async double buffer. smem pitch 80B (conflict-free LDSM).
// smem per buffer: Ah(10240) Al(10240) Bh(10240) Bl(10240) = 40960; x2 = 81920.
// ============================================================================
#define GEMM_SMEM 81920

template <int MODE>
__global__ __launch_bounds__(256, 2)
void gemm_tc(const float* __restrict__ bias, float* __restrict__ Cout)
{
    const __nv_bfloat16* Ah = (MODE == 0) ? g_xh : g_oh;
    const __nv_bfloat16* Al = (MODE == 0) ? g_xl : g_ol;
    const __nv_bfloat16* Bh = (MODE == 0) ? g_wt1h : g_wt2h;
    const __nv_bfloat16* Bl = (MODE == 0) ? g_wt1l : g_wt2l;
    float* C    = (MODE == 0) ? g_qkv : Cout;
    const int N = (MODE == 0) ? D3 : EMB;
    const int K = EMB;

    extern __shared__ char smem[];
    const uint32_t sb = smem_to_u32(smem);
    const int tid = threadIdx.x;
    const int wid = tid >> 5, lane = tid & 31;
    const int wm = wid & 3, wn = wid >> 2;
    const int m0 = blockIdx.y * 128, n0 = blockIdx.x * 128;

    // --- per-thread cp.async chunk descriptors (8 x 16B per stage) ---
    const __nv_bfloat16* csrc[8];
    uint32_t cdst[8];
#pragma unroll
    for (int i = 0; i < 8; i++) {
        int g = i * 256 + tid;
        int sub = g >> 9, c = g & 511, row = c >> 2, ch = c & 3;
        const __nv_bfloat16* bp =
            (sub == 0) ? Ah + (long)m0 * K :
            (sub == 1) ? Al + (long)m0 * K :
            (sub == 2) ? Bh + (long)n0 * K :
                         Bl + (long)n0 * K;
        csrc[i] = bp + (long)row * K + ch * 8;
        cdst[i] = sb + sub * 10240 + row * 80 + ch * 16;
    }

    // stage 0
#pragma unroll
    for (int i = 0; i < 8; i++) { CP_ASYNC16(cdst[i], csrc[i]); csrc[i] += 32; }
    CP_COMMIT();

    // --- ldmatrix lane base addresses (byte offsets, buffer 0) ---
    // A m16k16 x4: lanes 0-15 rows m0-15 (k0-7), lanes 16-31 same rows (k8-15)
    const uint32_t a_base = sb + (wm * 32 + (lane & 15)) * 80 + (lane >> 4) * 16;
    // B n16k16 x4: lanes 0-15 rows n0-7 (k halves), lanes 16-31 rows n8-15
    const uint32_t b_base = sb + 20480 +
        (wn * 64 + (lane & 7) + ((lane >> 4) & 1) * 8) * 80 + ((lane >> 3) & 1) * 16;

    float acc[2][8][4];
#pragma unroll
    for (int mf = 0; mf < 2; mf++)
#pragma unroll
        for (int nf = 0; nf < 8; nf++)
#pragma unroll
            for (int q = 0; q < 4; q++) acc[mf][nf][q] = 0.f;

    for (int ck = 0; ck < NCK; ck++) {
        const int buf = ck & 1;
        __syncthreads();                       // everyone done reading buf^1
        if (ck + 1 < NCK) {
            const uint32_t bo = (buf ^ 1) * 40960;
#pragma unroll
            for (int i = 0; i < 8; i++) { CP_ASYNC16(cdst[i] + bo, csrc[i]); csrc[i] += 32; }
            CP_COMMIT();
            CP_WAIT1();                        // stage ck landed
        } else {
            CP_WAIT0();
        }
        __syncthreads();                       // stage ck visible to all

        const uint32_t bofs = buf * 40960;
#pragma unroll
        for (int kk = 0; kk < 2; kk++) {
            const uint32_t ko = bofs + kk * 32;
            uint32_t ah[2][4], al[2][4];
#pragma unroll
            for (int mf = 0; mf < 2; mf++) {
                const uint32_t ao = a_base + mf * 1280 + ko;
                LDSM_X4(ah[mf][0], ah[mf][1], ah[mf][2], ah[mf][3], ao);
                LDSM_X4(al[mf][0], al[mf][1], al[mf][2], al[mf][3], ao + 10240);
            }
#pragma unroll
            for (int nf = 0; nf < 4; nf++) {
                uint32_t bh4[4], bl4[4];
                const uint32_t bo2 = b_base + nf * 1280 + ko;
                LDSM_X4(bh4[0], bh4[1], bh4[2], bh4[3], bo2);
                LDSM_X4(bl4[0], bl4[1], bl4[2], bl4[3], bo2 + 10240);
#pragma unroll
                for (int mf = 0; mf < 2; mf++) {
                    MMA_BF16(acc[mf][nf * 2 + 0], ah[mf], bh4[0], bh4[1]);
                    MMA_BF16(acc[mf][nf * 2 + 0], ah[mf], bl4[0], bl4[1]);
                    MMA_BF16(acc[mf][nf * 2 + 0], al[mf], bh4[0], bh4[1]);
                    MMA_BF16(acc[mf][nf * 2 + 1], ah[mf], bh4[2], bh4[3]);
                    MMA_BF16(acc[mf][nf * 2 + 1], ah[mf], bl4[2], bl4[3]);
                    MMA_BF16(acc[mf][nf * 2 + 1], al[mf], bh4[2], bh4[3]);
                }
            }
        }
    }

    // --- epilogue + bias ---
    const int gid = lane >> 2, tig = lane & 3;
#pragma unroll
    for (int mf = 0; mf < 2; mf++) {
#pragma unroll
        for (int nf = 0; nf < 8; nf++) {
            const int col = n0 + wn * 64 + nf * 8 + tig * 2;
            const float bx0 = bias[col], bx1 = bias[col + 1];
            const int r0 = m0 + wm * 32 + mf * 16 + gid;
            float2 v0, v1;
            v0.x = acc[mf][nf][0] + bx0;  v0.y = acc[mf][nf][1] + bx1;
            v1.x = acc[mf][nf][2] + bx0;  v1.y = acc[mf][nf][3] + bx1;
            *(float2*)&C[(long)r0 * N + col] = v0;
            *(float2*)&C[(long)(r0 + 8) * N + col] = v1;
        }
    }
}

// ---------------------------------------------------------------------------
// Flash-attention fp32, causal (unchanged from Round 4: register-blocked 4x4).
// ---------------------------------------------------------------------------
#define PITCH 68
#define SMEM_ATTN (4 * 64 * PITCH * 4)

__global__ __launch_bounds__(256, 2)
void attn_kernel()
{
    extern __shared__ float sm[];
    float* QT = sm;
    float* KT = QT + 64 * PITCH;
    float* Vs = KT + 64 * PITCH;
    float* PT = Vs + 64 * PITCH;

    const int qt = gridDim.x - 1 - blockIdx.x;
    const int h  = blockIdx.y;
    const int b  = blockIdx.z;
    const int tid = threadIdx.x;
    const int tx = tid & 15;
    const int ty = tid >> 4;

    const float* base = g_qkv + (long)b * SEQ * D3 + h * HSZ;
    const float* qp = base;
    const float* kp = base + EMB;

    const int q0 = qt * 64;

#pragma unroll
    for (int idx = tid; idx < 1024; idx += 256) {
        int s  = idx >> 4;
        int d4 = (idx & 15) << 2;
        float4 q = *(const float4*)(qp + (long)(q0 + s) * D3 + d4);
        QT[(d4 + 0) * PITCH + s] = q.x;
        QT[(d4 + 1) * PITCH + s] = q.y;
        QT[(d4 + 2) * PITCH + s] = q.z;
        QT[(d4 + 3) * PITCH + s] = q.w;
    }

    float m[4], l[4], acc[4][4];
#pragma unroll
    for (int i = 0; i < 4; i++) {
        m[i] = -1e30f; l[i] = 0.f;
#pragma unroll
        for (int j = 0; j < 4; j++) acc[i][j] = 0.f;
    }

    for (int kt = 0; kt <= qt; kt++) {
        __syncthreads();
        const int k0 = kt * 64;
#pragma unroll
        for (int idx = tid; idx < 1024; idx += 256) {
            int s  = idx >> 4;
            int d4 = (idx & 15) << 2;
            const float* krow = kp + (long)(k0 + s) * D3 + d4;
            float4 kk = *(const float4*)krow;
            float4 vv = *(const float4*)(krow + EMB);
            KT[(d4 + 0) * PITCH + s] = kk.x;
            KT[(d4 + 1) * PITCH + s] = kk.y;
            KT[(d4 + 2) * PITCH + s] = kk.z;
            KT[(d4 + 3) * PITCH + s] = kk.w;
            *(float4*)&Vs[s * PITCH + d4] = vv;
        }
        __syncthreads();

        float sc[4][4];
#pragma unroll
        for (int i = 0; i < 4; i++)
#pragma unroll
            for (int j = 0; j < 4; j++) sc[i][j] = 0.f;

#pragma unroll 4
        for (int d = 0; d < 64; d++) {
            float4 a = *(const float4*)&QT[d * PITCH + ty * 4];
            float4 bq = *(const float4*)&KT[d * PITCH + tx * 4];
            float ra[4] = {a.x, a.y, a.z, a.w};
            float rb[4] = {bq.x, bq.y, bq.z, bq.w};
#pragma unroll
            for (int i = 0; i < 4; i++)
#pragma unroll
                for (int j = 0; j < 4; j++)
                    sc[i][j] += ra[i] * rb[j];
        }

        float rowm[4];
#pragma unroll
        for (int i = 0; i < 4; i++) {
            rowm[i] = -1e30f;
#pragma unroll
            for (int j = 0; j < 4; j++) {
                float v = sc[i][j] * 0.125f;
                if (kt == qt && (tx * 4 + j) > (ty * 4 + i)) v = -1e30f;
                sc[i][j] = v;
                rowm[i] = fmaxf(rowm[i], v);
            }
        }
#pragma unroll
        for (int ofs = 1; ofs < 16; ofs <<= 1)
#pragma unroll
            for (int i = 0; i < 4; i++)
                rowm[i] = fmaxf(rowm[i], __shfl_xor_sync(0xffffffffu, rowm[i], ofs));

        float esc[4], psum[4];
#pragma unroll
        for (int i = 0; i < 4; i++) {
            float mnew = fmaxf(m[i], rowm[i]);
            esc[i] = __expf(m[i] - mnew);
            m[i] = mnew;
            psum[i] = 0.f;
#pragma unroll
            for (int j = 0; j < 4; j++) {
                float p = __expf(sc[i][j] - mnew);
                psum[i] += p;
                PT[(tx * 4 + j) * PITCH + ty * 4 + i] = p;
            }
        }
#pragma unroll
        for (int ofs = 1; ofs < 16; ofs <<= 1)
#pragma unroll
            for (int i = 0; i < 4; i++)
                psum[i] += __shfl_xor_sync(0xffffffffu, psum[i], ofs);

#pragma unroll
        for (int i = 0; i < 4; i++) {
            l[i] = l[i] * esc[i] + psum[i];
#pragma unroll
            for (int j = 0; j < 4; j++) acc[i][j] *= esc[i];
        }

        __syncthreads();

#pragma unroll 4
        for (int k = 0; k < 64; k++) {
            float4 a = *(const float4*)&PT[k * PITCH + ty * 4];
            float4 bv = *(const float4*)&Vs[k * PITCH + tx * 4];
            float ra[4] = {a.x, a.y, a.z, a.w};
            float rb[4] = {bv.x, bv.y, bv.z, bv.w};
#pragma unroll
            for (int i = 0; i < 4; i++)
#pragma unroll
                for (int j = 0; j < 4; j++)
                    acc[i][j] += ra[i] * rb[j];
        }
    }

#pragma unroll
    for (int i = 0; i < 4; i++) {
        const float inv = 1.f / l[i];
        const int row = q0 + ty * 4 + i;
        float4 o;
        o.x = acc[i][0] * inv;
        o.y = acc[i][1] * inv;
        o.z = acc[i][2] * inv;
        o.w = acc[i][3] * inv;
        *(float4*)&g_obuf[(long)(b * SEQ + row) * EMB + h * HSZ + tx * 4] = o;
    }
}

// ---------------------------------------------------------------------------
extern "C" void kernel_launch(void* const* d_in, const int* in_sizes, int n_in,
                              void* d_out, int out_size)
{
    const float* x     = (const float*)d_in[0];
    const float* W_qkv = (const float*)d_in[1];
    const float* b_qkv = (const float*)d_in[2];
    const float* W_out = (const float*)d_in[3];
    const float* b_out = (const float*)d_in[4];
    float* out = (float*)d_out;

    // 0) weight transpose + bf16 hi/lo split; x split
    prep_wt<0><<<dim3(D3 / 32, EMB / 32), dim3(32, 8)>>>(W_qkv, EMB, D3);
    prep_wt<1><<<dim3(EMB / 32, EMB / 32), dim3(32, 8)>>>(W_out, EMB, EMB);
    prep_split<0><<<ROWS * EMB / 4 / 256, 256>>>(x);

    // 1) QKV projection on HMMA tensor cores
    cudaFuncSetAttribute(gemm_tc<0>, cudaFuncAttributeMaxDynamicSharedMemorySize, GEMM_SMEM);
    gemm_tc<0><<<dim3(D3 / 128, ROWS / 128), 256, GEMM_SMEM>>>(b_qkv, nullptr);

    // 2) causal flash attention -> g_obuf
    cudaFuncSetAttribute(attn_kernel, cudaFuncAttributeMaxDynamicSharedMemorySize, SMEM_ATTN);
    attn_kernel<<<dim3(SEQ / 64, NH, BATCH), 256, SMEM_ATTN>>>();

    // 2b) split attention output
    prep_split<1><<<ROWS * EMB / 4 / 256, 256>>>(nullptr);

    // 3) output projection on HMMA tensor cores
    cudaFuncSetAttribute(gemm_tc<1>, cudaFuncAttributeMaxDynamicSharedMemorySize, GEMM_SMEM);
    gemm_tc<1><<<dim3(EMB / 128, ROWS / 128), 256, GEMM_SMEM>>>(b_out, out);
}

// round 7
// speedup vs baseline: 4.7925x; 1.8137x over previous
#include <cuda_runtime.h>
#include <cuda_bf16.h>
#include <cstdint>

#define SEQ   2048
#define EMB   1024
#define NH    16
#define HSZ   64
#define BATCH 2
#define ROWS  (BATCH * SEQ)     // 4096
#define D3    (3 * EMB)         // 3072
#define NCK   (EMB / 32)        // 32 k-stages of BK=32 for projection GEMMs

// Scratch (device globals — no allocation allowed)
__device__ __nv_bfloat16 g_qkvh[ROWS * D3];  // qkv hi  [b*s][3*EMB]
__device__ __nv_bfloat16 g_qkvl[ROWS * D3];  // qkv lo
__device__ __nv_bfloat16 g_wt1h[D3 * EMB];   // W_qkv^T hi  [3072,1024] (K-major)
__device__ __nv_bfloat16 g_wt1l[D3 * EMB];
__device__ __nv_bfloat16 g_wt2h[EMB * EMB];  // W_out^T hi
__device__ __nv_bfloat16 g_wt2l[EMB * EMB];
__device__ __nv_bfloat16 g_xh[ROWS * EMB];   // x hi/lo
__device__ __nv_bfloat16 g_xl[ROWS * EMB];
__device__ __nv_bfloat16 g_oh[ROWS * EMB];   // attn-out hi/lo
__device__ __nv_bfloat16 g_ol[ROWS * EMB];

// ============================================================================
// asm helpers (plain sm_80+ PTX — legal on target sm_103)
// ============================================================================
__device__ __forceinline__ uint32_t smem_to_u32(const void* p) {
    uint32_t a;
    asm("{ .reg .u64 t; cvta.to.shared.u64 t, %1; cvt.u32.u64 %0, t; }"
        : "=r"(a) : "l"(p));
    return a;
}

#define CP_ASYNC16(dst, src) \
    asm volatile("cp.async.cg.shared.global [%0], [%1], 16;" \
                 :: "r"(dst), "l"(__cvta_generic_to_global(src)) : "memory")
#define CP_COMMIT() asm volatile("cp.async.commit_group;" ::: "memory")
#define CP_WAIT0()  asm volatile("cp.async.wait_group 0;" ::: "memory")
#define CP_WAIT1()  asm volatile("cp.async.wait_group 1;" ::: "memory")

#define LDSM_X4(r0, r1, r2, r3, addr) \
    asm volatile("ldmatrix.sync.aligned.m8n8.x4.shared.b16 {%0,%1,%2,%3}, [%4];" \
                 : "=r"(r0), "=r"(r1), "=r"(r2), "=r"(r3) : "r"(addr))
#define LDSM_X4T(r0, r1, r2, r3, addr) \
    asm volatile("ldmatrix.sync.aligned.m8n8.x4.trans.shared.b16 {%0,%1,%2,%3}, [%4];" \
                 : "=r"(r0), "=r"(r1), "=r"(r2), "=r"(r3) : "r"(addr))

#define MMA_BF16(d, a, b0v, b1v) \
    asm volatile("mma.sync.aligned.m16n8k16.row.col.f32.bf16.bf16.f32 " \
                 "{%0,%1,%2,%3}, {%4,%5,%6,%7}, {%8,%9}, {%0,%1,%2,%3};" \
                 : "+f"((d)[0]), "+f"((d)[1]), "+f"((d)[2]), "+f"((d)[3]) \
                 : "r"((a)[0]), "r"((a)[1]), "r"((a)[2]), "r"((a)[3]), \
                   "r"(b0v), "r"(b1v))

// pack two f32 -> bf16x2 (lo in low half)
__device__ __forceinline__ uint32_t pack_bf16x2(float lo, float hi) {
    uint32_t r;
    asm("cvt.rn.bf16x2.f32 %0, %1, %2;" : "=r"(r) : "f"(hi), "f"(lo));
    return r;
}

// ============================================================================
// Prep: Wt[n][k] = W[k][n], split into bf16 hi/lo. W is [K, N] row-major.
// ============================================================================
template <int MODE>
__global__ void prep_wt(const float* __restrict__ W, int K, int N)
{
    __nv_bfloat16* Wh = (MODE == 0) ? g_wt1h : g_wt2h;
    __nv_bfloat16* Wl = (MODE == 0) ? g_wt1l : g_wt2l;
    __shared__ float t[32][33];
    const int n0 = blockIdx.x * 32, k0 = blockIdx.y * 32;
    const int tx = threadIdx.x, ty = threadIdx.y;
#pragma unroll
    for (int j = 0; j < 32; j += 8)
        t[ty + j][tx] = W[(long)(k0 + ty + j) * N + n0 + tx];
    __syncthreads();
#pragma unroll
    for (int j = 0; j < 32; j += 8) {
        const int n = n0 + ty + j, k = k0 + tx;
        float v = t[tx][ty + j];
        __nv_bfloat16 h = __float2bfloat16(v);
        Wh[(long)n * K + k] = h;
        Wl[(long)n * K + k] = __float2bfloat16(v - __bfloat162float(h));
    }
}

// x -> g_xh/g_xl (elementwise hi/lo split)
__global__ void prep_split_x(const float* __restrict__ s)
{
    const int i = blockIdx.x * blockDim.x + threadIdx.x;   // float4 index
    float4 v = ((const float4*)s)[i];
    union { __nv_bfloat16 b[4]; uint2 u; } ph, pl;
    ph.b[0] = __float2bfloat16(v.x);
    ph.b[1] = __float2bfloat16(v.y);
    ph.b[2] = __float2bfloat16(v.z);
    ph.b[3] = __float2bfloat16(v.w);
    pl.b[0] = __float2bfloat16(v.x - __bfloat162float(ph.b[0]));
    pl.b[1] = __float2bfloat16(v.y - __bfloat162float(ph.b[1]));
    pl.b[2] = __float2bfloat16(v.z - __bfloat162float(ph.b[2]));
    pl.b[3] = __float2bfloat16(v.w - __bfloat162float(ph.b[3]));
    ((uint2*)g_xh)[i] = ph.u;
    ((uint2*)g_xl)[i] = pl.u;
}

// ============================================================================
// HMMA GEMM + bias. 3-MMA split. CTA 128x128, BK=32, 8 warps (4m x 2n).
// MODE 0: A=g_xh/l, B=g_wt1*, writes g_qkvh/g_qkvl (bf16 hi/lo split of result)
// MODE 1: A=g_oh/l, B=g_wt2*, writes fp32 Cout (+bias)
// ============================================================================
#define GEMM_SMEM 81920

template <int MODE>
__global__ __launch_bounds__(256, 2)
void gemm_tc(const float* __restrict__ bias, float* __restrict__ Cout)
{
    const __nv_bfloat16* Ah = (MODE == 0) ? g_xh : g_oh;
    const __nv_bfloat16* Al = (MODE == 0) ? g_xl : g_ol;
    const __nv_bfloat16* Bh = (MODE == 0) ? g_wt1h : g_wt2h;
    const __nv_bfloat16* Bl = (MODE == 0) ? g_wt1l : g_wt2l;
    const int N = (MODE == 0) ? D3 : EMB;
    const int K = EMB;

    extern __shared__ char smem[];
    const uint32_t sb = smem_to_u32(smem);
    const int tid = threadIdx.x;
    const int wid = tid >> 5, lane = tid & 31;
    const int wm = wid & 3, wn = wid >> 2;
    const int m0 = blockIdx.y * 128, n0 = blockIdx.x * 128;

    const __nv_bfloat16* csrc[8];
    uint32_t cdst[8];
#pragma unroll
    for (int i = 0; i < 8; i++) {
        int g = i * 256 + tid;
        int sub = g >> 9, c = g & 511, row = c >> 2, ch = c & 3;
        const __nv_bfloat16* bp =
            (sub == 0) ? Ah + (long)m0 * K :
            (sub == 1) ? Al + (long)m0 * K :
            (sub == 2) ? Bh + (long)n0 * K :
                         Bl + (long)n0 * K;
        csrc[i] = bp + (long)row * K + ch * 8;
        cdst[i] = sb + sub * 10240 + row * 80 + ch * 16;
    }

#pragma unroll
    for (int i = 0; i < 8; i++) { CP_ASYNC16(cdst[i], csrc[i]); csrc[i] += 32; }
    CP_COMMIT();

    const uint32_t a_base = sb + (wm * 32 + (lane & 15)) * 80 + (lane >> 4) * 16;
    const uint32_t b_base = sb + 20480 +
        (wn * 64 + (lane & 7) + ((lane >> 4) & 1) * 8) * 80 + ((lane >> 3) & 1) * 16;

    float acc[2][8][4];
#pragma unroll
    for (int mf = 0; mf < 2; mf++)
#pragma unroll
        for (int nf = 0; nf < 8; nf++)
#pragma unroll
            for (int q = 0; q < 4; q++) acc[mf][nf][q] = 0.f;

    for (int ck = 0; ck < NCK; ck++) {
        const int buf = ck & 1;
        __syncthreads();
        if (ck + 1 < NCK) {
            const uint32_t bo = (buf ^ 1) * 40960;
#pragma unroll
            for (int i = 0; i < 8; i++) { CP_ASYNC16(cdst[i] + bo, csrc[i]); csrc[i] += 32; }
            CP_COMMIT();
            CP_WAIT1();
        } else {
            CP_WAIT0();
        }
        __syncthreads();

        const uint32_t bofs = buf * 40960;
#pragma unroll
        for (int kk = 0; kk < 2; kk++) {
            const uint32_t ko = bofs + kk * 32;
            uint32_t ah[2][4], al[2][4];
#pragma unroll
            for (int mf = 0; mf < 2; mf++) {
                const uint32_t ao = a_base + mf * 1280 + ko;
                LDSM_X4(ah[mf][0], ah[mf][1], ah[mf][2], ah[mf][3], ao);
                LDSM_X4(al[mf][0], al[mf][1], al[mf][2], al[mf][3], ao + 10240);
            }
#pragma unroll
            for (int nf = 0; nf < 4; nf++) {
                uint32_t bh4[4], bl4[4];
                const uint32_t bo2 = b_base + nf * 1280 + ko;
                LDSM_X4(bh4[0], bh4[1], bh4[2], bh4[3], bo2);
                LDSM_X4(bl4[0], bl4[1], bl4[2], bl4[3], bo2 + 10240);
#pragma unroll
                for (int mf = 0; mf < 2; mf++) {
                    MMA_BF16(acc[mf][nf * 2 + 0], ah[mf], bh4[0], bh4[1]);
                    MMA_BF16(acc[mf][nf * 2 + 0], ah[mf], bl4[0], bl4[1]);
                    MMA_BF16(acc[mf][nf * 2 + 0], al[mf], bh4[0], bh4[1]);
                    MMA_BF16(acc[mf][nf * 2 + 1], ah[mf], bh4[2], bh4[3]);
                    MMA_BF16(acc[mf][nf * 2 + 1], ah[mf], bl4[2], bl4[3]);
                    MMA_BF16(acc[mf][nf * 2 + 1], al[mf], bh4[2], bh4[3]);
                }
            }
        }
    }

    const int gid = lane >> 2, tig = lane & 3;
#pragma unroll
    for (int mf = 0; mf < 2; mf++) {
#pragma unroll
        for (int nf = 0; nf < 8; nf++) {
            const int col = n0 + wn * 64 + nf * 8 + tig * 2;
            const float bx0 = bias[col], bx1 = bias[col + 1];
            const int r0 = m0 + wm * 32 + mf * 16 + gid;
            float v00 = acc[mf][nf][0] + bx0, v01 = acc[mf][nf][1] + bx1;
            float v10 = acc[mf][nf][2] + bx0, v11 = acc[mf][nf][3] + bx1;
            if (MODE == 1) {
                float2 a0 = {v00, v01}, a1 = {v10, v11};
                *(float2*)&Cout[(long)r0 * N + col] = a0;
                *(float2*)&Cout[(long)(r0 + 8) * N + col] = a1;
            } else {
                // split into bf16 hi/lo, write packed pairs
                uint32_t h0 = pack_bf16x2(v00, v01);
                uint32_t h1 = pack_bf16x2(v10, v11);
                float hf00 = __uint_as_float(h0 << 16);
                float hf01 = __uint_as_float(h0 & 0xffff0000u);
                float hf10 = __uint_as_float(h1 << 16);
                float hf11 = __uint_as_float(h1 & 0xffff0000u);
                uint32_t l0 = pack_bf16x2(v00 - hf00, v01 - hf01);
                uint32_t l1 = pack_bf16x2(v10 - hf10, v11 - hf11);
                *(uint32_t*)&g_qkvh[(long)r0 * N + col] = h0;
                *(uint32_t*)&g_qkvl[(long)r0 * N + col] = l0;
                *(uint32_t*)&g_qkvh[(long)(r0 + 8) * N + col] = h1;
                *(uint32_t*)&g_qkvl[(long)(r0 + 8) * N + col] = l1;
            }
        }
    }
}

// ============================================================================
// HMMA flash attention, causal, split hi/lo 3-MMA everywhere.
// Q tile 128 x K tile 64, hs=64, 256 threads (8 warps x 16 q-rows).
// smem (pitch 144B): Qh Ql [128x64], Kh Kl Vh Vl [64x64]; K,V natural layout.
// QK: A=Q(ldsm), B=K(ldsm).  PV: A=P(from C-frags, reg repack), B=V(ldsm trans).
// Output: hi/lo bf16 to g_oh/g_ol.
// ============================================================================
#define APITCH 144
#define ATTN_SMEM (2*128*APITCH + 4*64*APITCH)   // 36864 + 36864 = 73728

__global__ __launch_bounds__(256, 2)
void attn_tc()
{
    extern __shared__ char smem[];
    const uint32_t sb = smem_to_u32(smem);
    const uint32_t sQ = sb;                 // Qh; Ql at +18432
    const uint32_t sK = sb + 36864;         // Kh; Kl +9216; Vh +18432; Vl +27648

    const int qt = gridDim.x - 1 - blockIdx.x;   // long blocks first
    const int h  = blockIdx.y;
    const int b  = blockIdx.z;
    const int tid = threadIdx.x;
    const int wid = tid >> 5, lane = tid & 31;
    const int gid = lane >> 2, tig = lane & 3;
    const int q0 = qt * 128;
    const long rowbase = (long)b * SEQ;

    // ---- Q tile load (once): 2 subtiles x 128 rows x 8 chunks ----
#pragma unroll
    for (int it = 0; it < 8; it++) {
        int g = it * 256 + tid;
        int sub = g >> 10, rem = g & 1023, row = rem >> 3, ch = rem & 7;
        const __nv_bfloat16* src = (sub ? g_qkvl : g_qkvh) +
            (rowbase + q0 + row) * D3 + h * HSZ + ch * 8;
        CP_ASYNC16(sQ + sub * 18432 + row * APITCH + ch * 16, src);
    }
    CP_COMMIT();

    // ldmatrix bases
    const uint32_t a_base = sQ + (wid * 16 + (lane & 15)) * APITCH + (lane >> 4) * 16;
    const uint32_t bk_base = sK + ((lane & 7) + ((lane >> 4) & 1) * 8) * APITCH
                              + ((lane >> 3) & 1) * 16;
    const uint32_t v_base = sK + 18432 + ((lane & 7) + ((lane >> 3) & 1) * 8) * APITCH
                              + (lane >> 4) * 16;

    float oacc[8][4];
#pragma unroll
    for (int df = 0; df < 8; df++)
#pragma unroll
        for (int q = 0; q < 4; q++) oacc[df][q] = 0.f;
    float mrow[2] = {-1e30f, -1e30f};
    float lrow[2] = {0.f, 0.f};

    const int qr0 = q0 + wid * 16 + gid;       // this thread's rows
    const int qr1 = qr0 + 8;
    const int nk = 2 * qt + 2;

    for (int kt = 0; kt < nk; kt++) {
        const int k0 = kt * 64;
        __syncthreads();     // previous stage's PV done
        // ---- K/V stage load: 4 subtiles x 64 rows x 8 chunks ----
#pragma unroll
        for (int it = 0; it < 8; it++) {
            int g = it * 256 + tid;
            int sub = g >> 9, rem = g & 511, row = rem >> 3, ch = rem & 7;
            const __nv_bfloat16* base = (sub & 1) ? g_qkvl : g_qkvh;
            const int colb = (sub >= 2) ? (2 * EMB + h * HSZ) : (EMB + h * HSZ);
            CP_ASYNC16(sK + sub * 9216 + row * APITCH + ch * 16,
                       base + (rowbase + k0 + row) * D3 + colb + ch * 8);
        }
        CP_COMMIT();
        CP_WAIT0();
        __syncthreads();

        // ---- QK^T scores ----
        float sacc[8][4];
#pragma unroll
        for (int nf = 0; nf < 8; nf++)
#pragma unroll
            for (int q = 0; q < 4; q++) sacc[nf][q] = 0.f;

#pragma unroll
        for (int ks = 0; ks < 4; ks++) {
            uint32_t ah[4], al[4];
            const uint32_t ao = a_base + ks * 32;
            LDSM_X4(ah[0], ah[1], ah[2], ah[3], ao);
            LDSM_X4(al[0], al[1], al[2], al[3], ao + 18432);
#pragma unroll
            for (int nb = 0; nb < 4; nb++) {
                uint32_t bh4[4], bl4[4];
                const uint32_t bo = bk_base + nb * (16 * APITCH) + ks * 32;
                LDSM_X4(bh4[0], bh4[1], bh4[2], bh4[3], bo);
                LDSM_X4(bl4[0], bl4[1], bl4[2], bl4[3], bo + 9216);
                MMA_BF16(sacc[nb * 2 + 0], ah, bh4[0], bh4[1]);
                MMA_BF16(sacc[nb * 2 + 0], ah, bl4[0], bl4[1]);
                MMA_BF16(sacc[nb * 2 + 0], al, bh4[0], bh4[1]);
                MMA_BF16(sacc[nb * 2 + 1], ah, bh4[2], bh4[3]);
                MMA_BF16(sacc[nb * 2 + 1], ah, bl4[2], bl4[3]);
                MMA_BF16(sacc[nb * 2 + 1], al, bh4[2], bh4[3]);
            }
        }

        // ---- scale + causal mask + row max ----
        const bool maskst = (kt >= 2 * qt);
        float tm0 = -1e30f, tm1 = -1e30f;
#pragma unroll
        for (int nf = 0; nf < 8; nf++) {
            const int c = k0 + nf * 8 + 2 * tig;
            float v0 = sacc[nf][0] * 0.125f;
            float v1 = sacc[nf][1] * 0.125f;
            float v2 = sacc[nf][2] * 0.125f;
            float v3 = sacc[nf][3] * 0.125f;
            if (maskst) {
                if (c     > qr0) v0 = -1e30f;
                if (c + 1 > qr0) v1 = -1e30f;
                if (c     > qr1) v2 = -1e30f;
                if (c + 1 > qr1) v3 = -1e30f;
            }
            sacc[nf][0] = v0; sacc[nf][1] = v1;
            sacc[nf][2] = v2; sacc[nf][3] = v3;
            tm0 = fmaxf(tm0, fmaxf(v0, v1));
            tm1 = fmaxf(tm1, fmaxf(v2, v3));
        }
        tm0 = fmaxf(tm0, __shfl_xor_sync(0xffffffffu, tm0, 1));
        tm0 = fmaxf(tm0, __shfl_xor_sync(0xffffffffu, tm0, 2));
        tm1 = fmaxf(tm1, __shfl_xor_sync(0xffffffffu, tm1, 1));
        tm1 = fmaxf(tm1, __shfl_xor_sync(0xffffffffu, tm1, 2));

        const float mn0 = fmaxf(mrow[0], tm0);
        const float mn1 = fmaxf(mrow[1], tm1);
        const float esc0 = __expf(mrow[0] - mn0);
        const float esc1 = __expf(mrow[1] - mn1);
        mrow[0] = mn0; mrow[1] = mn1;
#pragma unroll
        for (int df = 0; df < 8; df++) {
            oacc[df][0] *= esc0; oacc[df][1] *= esc0;
            oacc[df][2] *= esc1; oacc[df][3] *= esc1;
        }

        // ---- exp + row sums (P left in sacc as fp32) ----
        float ps0 = 0.f, ps1 = 0.f;
#pragma unroll
        for (int nf = 0; nf < 8; nf++) {
            float p0 = __expf(sacc[nf][0] - mn0);
            float p1 = __expf(sacc[nf][1] - mn0);
            float p2 = __expf(sacc[nf][2] - mn1);
            float p3 = __expf(sacc[nf][3] - mn1);
            ps0 += p0 + p1; ps1 += p2 + p3;
            sacc[nf][0] = p0; sacc[nf][1] = p1;
            sacc[nf][2] = p2; sacc[nf][3] = p3;
        }
        ps0 += __shfl_xor_sync(0xffffffffu, ps0, 1);
        ps0 += __shfl_xor_sync(0xffffffffu, ps0, 2);
        ps1 += __shfl_xor_sync(0xffffffffu, ps1, 1);
        ps1 += __shfl_xor_sync(0xffffffffu, ps1, 2);
        lrow[0] = lrow[0] * esc0 + ps0;
        lrow[1] = lrow[1] * esc1 + ps1;

        // ---- PV: repack P C-frags -> A-frags (hi/lo), MMA with V (trans) ----
#pragma unroll
        for (int ks = 0; ks < 4; ks++) {
            const int f0 = 2 * ks, f1 = 2 * ks + 1;
            uint32_t pah[4], pal[4];
            {
                uint32_t u;
                u = pack_bf16x2(sacc[f0][0], sacc[f0][1]); pah[0] = u;
                pal[0] = pack_bf16x2(sacc[f0][0] - __uint_as_float(u << 16),
                                     sacc[f0][1] - __uint_as_float(u & 0xffff0000u));
                u = pack_bf16x2(sacc[f0][2], sacc[f0][3]); pah[1] = u;
                pal[1] = pack_bf16x2(sacc[f0][2] - __uint_as_float(u << 16),
                                     sacc[f0][3] - __uint_as_float(u & 0xffff0000u));
                u = pack_bf16x2(sacc[f1][0], sacc[f1][1]); pah[2] = u;
                pal[2] = pack_bf16x2(sacc[f1][0] - __uint_as_float(u << 16),
                                     sacc[f1][1] - __uint_as_float(u & 0xffff0000u));
                u = pack_bf16x2(sacc[f1][2], sacc[f1][3]); pah[3] = u;
                pal[3] = pack_bf16x2(sacc[f1][2] - __uint_as_float(u << 16),
                                     sacc[f1][3] - __uint_as_float(u & 0xffff0000u));
            }
#pragma unroll
            for (int nb = 0; nb < 4; nb++) {
                uint32_t vh4[4], vl4[4];
                const uint32_t vo = v_base + ks * (16 * APITCH) + nb * 32;
                LDSM_X4T(vh4[0], vh4[1], vh4[2], vh4[3], vo);
                LDSM_X4T(vl4[0], vl4[1], vl4[2], vl4[3], vo + 9216);
                MMA_BF16(oacc[nb * 2 + 0], pah, vh4[0], vh4[1]);
                MMA_BF16(oacc[nb * 2 + 0], pah, vl4[0], vl4[1]);
                MMA_BF16(oacc[nb * 2 + 0], pal, vh4[0], vh4[1]);
                MMA_BF16(oacc[nb * 2 + 1], pah, vh4[2], vh4[3]);
                MMA_BF16(oacc[nb * 2 + 1], pah, vl4[2], vl4[3]);
                MMA_BF16(oacc[nb * 2 + 1], pal, vh4[2], vh4[3]);
            }
        }
    }

    // ---- finalize: O = oacc/l, split hi/lo, write g_oh/g_ol ----
    const float inv0 = 1.f / lrow[0];
    const float inv1 = 1.f / lrow[1];
#pragma unroll
    for (int df = 0; df < 8; df++) {
        const int col = h * HSZ + df * 8 + 2 * tig;
        float v00 = oacc[df][0] * inv0, v01 = oacc[df][1] * inv0;
        float v10 = oacc[df][2] * inv1, v11 = oacc[df][3] * inv1;
        uint32_t h0 = pack_bf16x2(v00, v01);
        uint32_t h1 = pack_bf16x2(v10, v11);
        uint32_t l0 = pack_bf16x2(v00 - __uint_as_float(h0 << 16),
                                  v01 - __uint_as_float(h0 & 0xffff0000u));
        uint32_t l1 = pack_bf16x2(v10 - __uint_as_float(h1 << 16),
                                  v11 - __uint_as_float(h1 & 0xffff0000u));
        *(uint32_t*)&g_oh[(rowbase + qr0) * EMB + col] = h0;
        *(uint32_t*)&g_ol[(rowbase + qr0) * EMB + col] = l0;
        *(uint32_t*)&g_oh[(rowbase + qr1) * EMB + col] = h1;
        *(uint32_t*)&g_ol[(rowbase + qr1) * EMB + col] = l1;
    }
}

// ---------------------------------------------------------------------------
extern "C" void kernel_launch(void* const* d_in, const int* in_sizes, int n_in,
                              void* d_out, int out_size)
{
    const float* x     = (const float*)d_in[0];
    const float* W_qkv = (const float*)d_in[1];
    const float* b_qkv = (const float*)d_in[2];
    const float* W_out = (const float*)d_in[3];
    const float* b_out = (const float*)d_in[4];
    float* out = (float*)d_out;

    // 0) weight transpose + split; x split
    prep_wt<0><<<dim3(D3 / 32, EMB / 32), dim3(32, 8)>>>(W_qkv, EMB, D3);
    prep_wt<1><<<dim3(EMB / 32, EMB / 32), dim3(32, 8)>>>(W_out, EMB, EMB);
    prep_split_x<<<ROWS * EMB / 4 / 256, 256>>>(x);

    // 1) QKV projection (HMMA), emits bf16 hi/lo qkv
    cudaFuncSetAttribute(gemm_tc<0>, cudaFuncAttributeMaxDynamicSharedMemorySize, GEMM_SMEM);
    gemm_tc<0><<<dim3(D3 / 128, ROWS / 128), 256, GEMM_SMEM>>>(b_qkv, nullptr);

    // 2) causal flash attention (HMMA), emits bf16 hi/lo O
    cudaFuncSetAttribute(attn_tc, cudaFuncAttributeMaxDynamicSharedMemorySize, ATTN_SMEM);
    attn_tc<<<dim3(SEQ / 128, NH, BATCH), 256, ATTN_SMEM>>>();

    // 3) output projection (HMMA), fp32 out + bias
    cudaFuncSetAttribute(gemm_tc<1>, cudaFuncAttributeMaxDynamicSharedMemorySize, GEMM_SMEM);
    gemm_tc<1><<<dim3(EMB / 128, ROWS / 128), 256, GEMM_SMEM>>>(b_out, out);
}

// round 8
// speedup vs baseline: 5.0308x; 1.0497x over previous
#include <cuda_runtime.h>
#include <cuda_bf16.h>
#include <cstdint>

#define SEQ   2048
#define EMB   1024
#define NH    16
#define HSZ   64
#define BATCH 2
#define ROWS  (BATCH * SEQ)     // 4096
#define D3    (3 * EMB)         // 3072
#define NCK   (EMB / 32)        // 32 k-stages of BK=32 for projection GEMMs

// Scratch (device globals — no allocation allowed)
__device__ __nv_bfloat16 g_qkvh[ROWS * D3];  // qkv hi  [b*s][3*EMB]
__device__ __nv_bfloat16 g_qkvl[ROWS * D3];  // qkv lo
__device__ __nv_bfloat16 g_wt1h[D3 * EMB];   // W_qkv^T hi  [3072,1024] (K-major)
__device__ __nv_bfloat16 g_wt1l[D3 * EMB];
__device__ __nv_bfloat16 g_wt2h[EMB * EMB];  // W_out^T hi
__device__ __nv_bfloat16 g_wt2l[EMB * EMB];
__device__ __nv_bfloat16 g_xh[ROWS * EMB];   // x hi/lo
__device__ __nv_bfloat16 g_xl[ROWS * EMB];
__device__ __nv_bfloat16 g_oh[ROWS * EMB];   // attn-out hi/lo
__device__ __nv_bfloat16 g_ol[ROWS * EMB];

// ============================================================================
// asm helpers (plain sm_80+ PTX — legal on target sm_103)
// ============================================================================
__device__ __forceinline__ uint32_t smem_to_u32(const void* p) {
    uint32_t a;
    asm("{ .reg .u64 t; cvta.to.shared.u64 t, %1; cvt.u32.u64 %0, t; }"
        : "=r"(a) : "l"(p));
    return a;
}

#define CP_ASYNC16(dst, src) \
    asm volatile("cp.async.cg.shared.global [%0], [%1], 16;" \
                 :: "r"(dst), "l"(__cvta_generic_to_global(src)) : "memory")
#define CP_COMMIT() asm volatile("cp.async.commit_group;" ::: "memory")
#define CP_WAIT0()  asm volatile("cp.async.wait_group 0;" ::: "memory")
#define CP_WAIT1()  asm volatile("cp.async.wait_group 1;" ::: "memory")
#define CP_WAIT2()  asm volatile("cp.async.wait_group 2;" ::: "memory")

#define LDSM_X4(r0, r1, r2, r3, addr) \
    asm volatile("ldmatrix.sync.aligned.m8n8.x4.shared.b16 {%0,%1,%2,%3}, [%4];" \
                 : "=r"(r0), "=r"(r1), "=r"(r2), "=r"(r3) : "r"(addr))
#define LDSM_X4T(r0, r1, r2, r3, addr) \
    asm volatile("ldmatrix.sync.aligned.m8n8.x4.trans.shared.b16 {%0,%1,%2,%3}, [%4];" \
                 : "=r"(r0), "=r"(r1), "=r"(r2), "=r"(r3) : "r"(addr))

#define MMA_BF16(d, a, b0v, b1v) \
    asm volatile("mma.sync.aligned.m16n8k16.row.col.f32.bf16.bf16.f32 " \
                 "{%0,%1,%2,%3}, {%4,%5,%6,%7}, {%8,%9}, {%0,%1,%2,%3};" \
                 : "+f"((d)[0]), "+f"((d)[1]), "+f"((d)[2]), "+f"((d)[3]) \
                 : "r"((a)[0]), "r"((a)[1]), "r"((a)[2]), "r"((a)[3]), \
                   "r"(b0v), "r"(b1v))

// pack two f32 -> bf16x2 (first arg in low half)
__device__ __forceinline__ uint32_t pack_bf16x2(float lo, float hi) {
    uint32_t r;
    asm("cvt.rn.bf16x2.f32 %0, %1, %2;" : "=r"(r) : "f"(hi), "f"(lo));
    return r;
}

// ============================================================================
// Prep: Wt[n][k] = W[k][n], split into bf16 hi/lo. W is [K, N] row-major.
// ============================================================================
template <int MODE>
__global__ void prep_wt(const float* __restrict__ W, int K, int N)
{
    __nv_bfloat16* Wh = (MODE == 0) ? g_wt1h : g_wt2h;
    __nv_bfloat16* Wl = (MODE == 0) ? g_wt1l : g_wt2l;
    __shared__ float t[32][33];
    const int n0 = blockIdx.x * 32, k0 = blockIdx.y * 32;
    const int tx = threadIdx.x, ty = threadIdx.y;
#pragma unroll
    for (int j = 0; j < 32; j += 8)
        t[ty + j][tx] = W[(long)(k0 + ty + j) * N + n0 + tx];
    __syncthreads();
#pragma unroll
    for (int j = 0; j < 32; j += 8) {
        const int n = n0 + ty + j, k = k0 + tx;
        float v = t[tx][ty + j];
        __nv_bfloat16 h = __float2bfloat16(v);
        Wh[(long)n * K + k] = h;
        Wl[(long)n * K + k] = __float2bfloat16(v - __bfloat162float(h));
    }
}

// x -> g_xh/g_xl (elementwise hi/lo split)
__global__ void prep_split_x(const float* __restrict__ s)
{
    const int i = blockIdx.x * blockDim.x + threadIdx.x;   // float4 index
    float4 v = ((const float4*)s)[i];
    union { __nv_bfloat16 b[4]; uint2 u; } ph, pl;
    ph.b[0] = __float2bfloat16(v.x);
    ph.b[1] = __float2bfloat16(v.y);
    ph.b[2] = __float2bfloat16(v.z);
    ph.b[3] = __float2bfloat16(v.w);
    pl.b[0] = __float2bfloat16(v.x - __bfloat162float(ph.b[0]));
    pl.b[1] = __float2bfloat16(v.y - __bfloat162float(ph.b[1]));
    pl.b[2] = __float2bfloat16(v.z - __bfloat162float(ph.b[2]));
    pl.b[3] = __float2bfloat16(v.w - __bfloat162float(ph.b[3]));
    ((uint2*)g_xh)[i] = ph.u;
    ((uint2*)g_xl)[i] = pl.u;
}

// ============================================================================
// HMMA GEMM + bias. 3-MMA split. CTA 128x128, BK=32, 8 warps (4m x 2n).
// Single __syncthreads per k-stage: [wait0; sync; issue-next; compute].
// MODE 0: A=g_xh/l, B=g_wt1*, writes g_qkvh/g_qkvl
// MODE 1: A=g_oh/l, B=g_wt2*, writes fp32 Cout (+bias)
// ============================================================================
#define GEMM_SMEM 81920

template <int MODE>
__global__ __launch_bounds__(256, 2)
void gemm_tc(const float* __restrict__ bias, float* __restrict__ Cout)
{
    const __nv_bfloat16* Ah = (MODE == 0) ? g_xh : g_oh;
    const __nv_bfloat16* Al = (MODE == 0) ? g_xl : g_ol;
    const __nv_bfloat16* Bh = (MODE == 0) ? g_wt1h : g_wt2h;
    const __nv_bfloat16* Bl = (MODE == 0) ? g_wt1l : g_wt2l;
    const int N = (MODE == 0) ? D3 : EMB;
    const int K = EMB;

    extern __shared__ char smem[];
    const uint32_t sb = smem_to_u32(smem);
    const int tid = threadIdx.x;
    const int wid = tid >> 5, lane = tid & 31;
    const int wm = wid & 3, wn = wid >> 2;
    const int m0 = blockIdx.y * 128, n0 = blockIdx.x * 128;

    const __nv_bfloat16* csrc[8];
    uint32_t cdst[8];
#pragma unroll
    for (int i = 0; i < 8; i++) {
        int g = i * 256 + tid;
        int sub = g >> 9, c = g & 511, row = c >> 2, ch = c & 3;
        const __nv_bfloat16* bp =
            (sub == 0) ? Ah + (long)m0 * K :
            (sub == 1) ? Al + (long)m0 * K :
            (sub == 2) ? Bh + (long)n0 * K :
                         Bl + (long)n0 * K;
        csrc[i] = bp + (long)row * K + ch * 8;
        cdst[i] = sb + sub * 10240 + row * 80 + ch * 16;
    }

#pragma unroll
    for (int i = 0; i < 8; i++) { CP_ASYNC16(cdst[i], csrc[i]); csrc[i] += 32; }
    CP_COMMIT();

    const uint32_t a_base = sb + (wm * 32 + (lane & 15)) * 80 + (lane >> 4) * 16;
    const uint32_t b_base = sb + 20480 +
        (wn * 64 + (lane & 7) + ((lane >> 4) & 1) * 8) * 80 + ((lane >> 3) & 1) * 16;

    float acc[2][8][4];
#pragma unroll
    for (int mf = 0; mf < 2; mf++)
#pragma unroll
        for (int nf = 0; nf < 8; nf++)
#pragma unroll
            for (int q = 0; q < 4; q++) acc[mf][nf][q] = 0.f;

    for (int ck = 0; ck < NCK; ck++) {
        const int buf = ck & 1;
        CP_WAIT0();            // stage ck landed
        __syncthreads();       // visible to all; prev compute (reads buf^1) done
        if (ck + 1 < NCK) {
            const uint32_t bo = (buf ^ 1) * 40960;
#pragma unroll
            for (int i = 0; i < 8; i++) { CP_ASYNC16(cdst[i] + bo, csrc[i]); csrc[i] += 32; }
            CP_COMMIT();
        }

        const uint32_t bofs = buf * 40960;
#pragma unroll
        for (int kk = 0; kk < 2; kk++) {
            const uint32_t ko = bofs + kk * 32;
            uint32_t ah[2][4], al[2][4];
#pragma unroll
            for (int mf = 0; mf < 2; mf++) {
                const uint32_t ao = a_base + mf * 1280 + ko;
                LDSM_X4(ah[mf][0], ah[mf][1], ah[mf][2], ah[mf][3], ao);
                LDSM_X4(al[mf][0], al[mf][1], al[mf][2], al[mf][3], ao + 10240);
            }
#pragma unroll
            for (int nf = 0; nf < 4; nf++) {
                uint32_t bh4[4], bl4[4];
                const uint32_t bo2 = b_base + nf * 1280 + ko;
                LDSM_X4(bh4[0], bh4[1], bh4[2], bh4[3], bo2);
                LDSM_X4(bl4[0], bl4[1], bl4[2], bl4[3], bo2 + 10240);
#pragma unroll
                for (int mf = 0; mf < 2; mf++) {
                    MMA_BF16(acc[mf][nf * 2 + 0], ah[mf], bh4[0], bh4[1]);
                    MMA_BF16(acc[mf][nf * 2 + 0], ah[mf], bl4[0], bl4[1]);
                    MMA_BF16(acc[mf][nf * 2 + 0], al[mf], bh4[0], bh4[1]);
                    MMA_BF16(acc[mf][nf * 2 + 1], ah[mf], bh4[2], bh4[3]);
                    MMA_BF16(acc[mf][nf * 2 + 1], ah[mf], bl4[2], bl4[3]);
                    MMA_BF16(acc[mf][nf * 2 + 1], al[mf], bh4[2], bh4[3]);
                }
            }
        }
    }

    const int gid = lane >> 2, tig = lane & 3;
#pragma unroll
    for (int mf = 0; mf < 2; mf++) {
#pragma unroll
        for (int nf = 0; nf < 8; nf++) {
            const int col = n0 + wn * 64 + nf * 8 + tig * 2;
            const float bx0 = bias[col], bx1 = bias[col + 1];
            const int r0 = m0 + wm * 32 + mf * 16 + gid;
            float v00 = acc[mf][nf][0] + bx0, v01 = acc[mf][nf][1] + bx1;
            float v10 = acc[mf][nf][2] + bx0, v11 = acc[mf][nf][3] + bx1;
            if (MODE == 1) {
                float2 a0 = {v00, v01}, a1 = {v10, v11};
                *(float2*)&Cout[(long)r0 * N + col] = a0;
                *(float2*)&Cout[(long)(r0 + 8) * N + col] = a1;
            } else {
                uint32_t h0 = pack_bf16x2(v00, v01);
                uint32_t h1 = pack_bf16x2(v10, v11);
                float hf00 = __uint_as_float(h0 << 16);
                float hf01 = __uint_as_float(h0 & 0xffff0000u);
                float hf10 = __uint_as_float(h1 << 16);
                float hf11 = __uint_as_float(h1 & 0xffff0000u);
                uint32_t l0 = pack_bf16x2(v00 - hf00, v01 - hf01);
                uint32_t l1 = pack_bf16x2(v10 - hf10, v11 - hf11);
                *(uint32_t*)&g_qkvh[(long)r0 * N + col] = h0;
                *(uint32_t*)&g_qkvl[(long)r0 * N + col] = l0;
                *(uint32_t*)&g_qkvh[(long)(r0 + 8) * N + col] = h1;
                *(uint32_t*)&g_qkvl[(long)(r0 + 8) * N + col] = l1;
            }
        }
    }
}

// ============================================================================
// HMMA flash attention, causal, split hi/lo 3-MMA, pipelined K/V stages.
// Q tile 128 x K tile 64, hs=64, 256 threads (8 warps x 16 q-rows).
// smem (pitch 144B): Qh Ql [128x64]; K double buffer (Kh Kl)x2; V double (Vh Vl)x2.
// Stage kt: issue V_kt, issue K_{kt+1}; wait<=2 (K_kt); sync; QK^T;
//           wait<=1 (V_kt); sync; softmax; PV.
// ============================================================================
#define APITCH 144
#define SQ_BYTES  (128 * APITCH)          // 18432 (one of Qh/Ql)
#define SKV_BYTES (64 * APITCH)           // 9216  (one of Kh/Kl/Vh/Vl)
#define ATTN_SMEM (2*SQ_BYTES + 4*SKV_BYTES + 4*SKV_BYTES)   // 110592

__global__ __launch_bounds__(256, 2)
void attn_tc()
{
    extern __shared__ char smem[];
    const uint32_t sb = smem_to_u32(smem);
    const uint32_t sQ = sb;                          // Qh; Ql +18432
    const uint32_t sK0 = sb + 2 * SQ_BYTES;          // K buf: +buf*18432 (Kh; Kl +9216)
    const uint32_t sV0 = sK0 + 4 * SKV_BYTES;        // V buf: +vbuf*18432 (Vh; Vl +9216)

    const int qt = gridDim.x - 1 - blockIdx.x;   // long blocks first
    const int h  = blockIdx.y;
    const int b  = blockIdx.z;
    const int tid = threadIdx.x;
    const int wid = tid >> 5, lane = tid & 31;
    const int gid = lane >> 2, tig = lane & 3;
    const int q0 = qt * 128;
    const long rowbase = (long)b * SEQ;
    const int nk = 2 * qt + 2;

    // ---- Q tile load (group 1): 2 subtiles x 128 rows x 8 chunks ----
#pragma unroll
    for (int it = 0; it < 8; it++) {
        int g = it * 256 + tid;
        int sub = g >> 10, rem = g & 1023, row = rem >> 3, ch = rem & 7;
        const __nv_bfloat16* src = (sub ? g_qkvl : g_qkvh) +
            (rowbase + q0 + row) * D3 + h * HSZ + ch * 8;
        CP_ASYNC16(sQ + sub * SQ_BYTES + row * APITCH + ch * 16, src);
    }
    CP_COMMIT();

    // ---- K stage 0 load (group 2) ----
    {
        const int kr0 = 0;
#pragma unroll
        for (int it = 0; it < 4; it++) {
            int g = it * 256 + tid;
            int sub = g >> 9, rem = g & 511, row = rem >> 3, ch = rem & 7;
            const __nv_bfloat16* src = (sub ? g_qkvl : g_qkvh) +
                (rowbase + kr0 + row) * D3 + EMB + h * HSZ + ch * 8;
            CP_ASYNC16(sK0 + sub * SKV_BYTES + row * APITCH + ch * 16, src);
        }
        CP_COMMIT();
    }

    // ldmatrix lane offsets (relative)
    const uint32_t a_base = sQ + (wid * 16 + (lane & 15)) * APITCH + (lane >> 4) * 16;
    const uint32_t bk_off = ((lane & 7) + ((lane >> 4) & 1) * 8) * APITCH
                              + ((lane >> 3) & 1) * 16;
    const uint32_t v_off = ((lane & 7) + ((lane >> 3) & 1) * 8) * APITCH
                              + (lane >> 4) * 16;

    float oacc[8][4];
#pragma unroll
    for (int df = 0; df < 8; df++)
#pragma unroll
        for (int q = 0; q < 4; q++) oacc[df][q] = 0.f;
    float mrow[2] = {-1e30f, -1e30f};
    float lrow[2] = {0.f, 0.f};

    const int qr0 = q0 + wid * 16 + gid;
    const int qr1 = qr0 + 8;

    for (int kt = 0; kt < nk; kt++) {
        const int k0 = kt * 64;
        const int buf = kt & 1;

        // ---- issue V_kt (one group) ----
        {
            const uint32_t vb = sV0 + buf * 2 * SKV_BYTES;
#pragma unroll
            for (int it = 0; it < 4; it++) {
                int g = it * 256 + tid;
                int sub = g >> 9, rem = g & 511, row = rem >> 3, ch = rem & 7;
                const __nv_bfloat16* src = (sub ? g_qkvl : g_qkvh) +
                    (rowbase + k0 + row) * D3 + 2 * EMB + h * HSZ + ch * 8;
                CP_ASYNC16(vb + sub * SKV_BYTES + row * APITCH + ch * 16, src);
            }
            CP_COMMIT();
        }
        // ---- issue K_{kt+1} (one group; clamped re-load on last stage) ----
        {
            const int kn0 = (kt + 1 < nk) ? (kt + 1) * 64 : 0;
            const uint32_t kb = sK0 + (buf ^ 1) * 2 * SKV_BYTES;
#pragma unroll
            for (int it = 0; it < 4; it++) {
                int g = it * 256 + tid;
                int sub = g >> 9, rem = g & 511, row = rem >> 3, ch = rem & 7;
                const __nv_bfloat16* src = (sub ? g_qkvl : g_qkvh) +
                    (rowbase + kn0 + row) * D3 + EMB + h * HSZ + ch * 8;
                CP_ASYNC16(kb + sub * SKV_BYTES + row * APITCH + ch * 16, src);
            }
            CP_COMMIT();
        }

        CP_WAIT2();            // K_kt (and Q on kt=0) landed
        __syncthreads();

        // ---- QK^T scores ----
        const uint32_t bk_base = sK0 + buf * 2 * SKV_BYTES + bk_off;
        float sacc[8][4];
#pragma unroll
        for (int nf = 0; nf < 8; nf++)
#pragma unroll
            for (int q = 0; q < 4; q++) sacc[nf][q] = 0.f;

#pragma unroll
        for (int ks = 0; ks < 4; ks++) {
            uint32_t ah[4], al[4];
            const uint32_t ao = a_base + ks * 32;
            LDSM_X4(ah[0], ah[1], ah[2], ah[3], ao);
            LDSM_X4(al[0], al[1], al[2], al[3], ao + SQ_BYTES);
#pragma unroll
            for (int nb = 0; nb < 4; nb++) {
                uint32_t bh4[4], bl4[4];
                const uint32_t bo = bk_base + nb * (16 * APITCH) + ks * 32;
                LDSM_X4(bh4[0], bh4[1], bh4[2], bh4[3], bo);
                LDSM_X4(bl4[0], bl4[1], bl4[2], bl4[3], bo + SKV_BYTES);
                MMA_BF16(sacc[nb * 2 + 0], ah, bh4[0], bh4[1]);
                MMA_BF16(sacc[nb * 2 + 0], ah, bl4[0], bl4[1]);
                MMA_BF16(sacc[nb * 2 + 0], al, bh4[0], bh4[1]);
                MMA_BF16(sacc[nb * 2 + 1], ah, bh4[2], bh4[3]);
                MMA_BF16(sacc[nb * 2 + 1], ah, bl4[2], bl4[3]);
                MMA_BF16(sacc[nb * 2 + 1], al, bh4[2], bh4[3]);
            }
        }

        CP_WAIT1();            // V_kt landed (K_{kt+1} still in flight)
        __syncthreads();

        // ---- scale + causal mask + row max ----
        const bool maskst = (kt >= 2 * qt);
        float tm0 = -1e30f, tm1 = -1e30f;
#pragma unroll
        for (int nf = 0; nf < 8; nf++) {
            const int c = k0 + nf * 8 + 2 * tig;
            float v0 = sacc[nf][0] * 0.125f;
            float v1 = sacc[nf][1] * 0.125f;
            float v2 = sacc[nf][2] * 0.125f;
            float v3 = sacc[nf][3] * 0.125f;
            if (maskst) {
                if (c     > qr0) v0 = -1e30f;
                if (c + 1 > qr0) v1 = -1e30f;
                if (c     > qr1) v2 = -1e30f;
                if (c + 1 > qr1) v3 = -1e30f;
            }
            sacc[nf][0] = v0; sacc[nf][1] = v1;
            sacc[nf][2] = v2; sacc[nf][3] = v3;
            tm0 = fmaxf(tm0, fmaxf(v0, v1));
            tm1 = fmaxf(tm1, fmaxf(v2, v3));
        }
        tm0 = fmaxf(tm0, __shfl_xor_sync(0xffffffffu, tm0, 1));
        tm0 = fmaxf(tm0, __shfl_xor_sync(0xffffffffu, tm0, 2));
        tm1 = fmaxf(tm1, __shfl_xor_sync(0xffffffffu, tm1, 1));
        tm1 = fmaxf(tm1, __shfl_xor_sync(0xffffffffu, tm1, 2));

        const float mn0 = fmaxf(mrow[0], tm0);
        const float mn1 = fmaxf(mrow[1], tm1);
        const float esc0 = __expf(mrow[0] - mn0);
        const float esc1 = __expf(mrow[1] - mn1);
        mrow[0] = mn0; mrow[1] = mn1;
#pragma unroll
        for (int df = 0; df < 8; df++) {
            oacc[df][0] *= esc0; oacc[df][1] *= esc0;
            oacc[df][2] *= esc1; oacc[df][3] *= esc1;
        }

        // ---- exp + row sums ----
        float ps0 = 0.f, ps1 = 0.f;
#pragma unroll
        for (int nf = 0; nf < 8; nf++) {
            float p0 = __expf(sacc[nf][0] - mn0);
            float p1 = __expf(sacc[nf][1] - mn0);
            float p2 = __expf(sacc[nf][2] - mn1);
            float p3 = __expf(sacc[nf][3] - mn1);
            ps0 += p0 + p1; ps1 += p2 + p3;
            sacc[nf][0] = p0; sacc[nf][1] = p1;
            sacc[nf][2] = p2; sacc[nf][3] = p3;
        }
        ps0 += __shfl_xor_sync(0xffffffffu, ps0, 1);
        ps0 += __shfl_xor_sync(0xffffffffu, ps0, 2);
        ps1 += __shfl_xor_sync(0xffffffffu, ps1, 1);
        ps1 += __shfl_xor_sync(0xffffffffu, ps1, 2);
        lrow[0] = lrow[0] * esc0 + ps0;
        lrow[1] = lrow[1] * esc1 + ps1;

        // ---- PV: repack P C-frags -> A-frags (hi/lo), MMA with V (trans) ----
        const uint32_t v_base = sV0 + buf * 2 * SKV_BYTES + v_off;
#pragma unroll
        for (int ks = 0; ks < 4; ks++) {
            const int f0 = 2 * ks, f1 = 2 * ks + 1;
            uint32_t pah[4], pal[4];
            {
                uint32_t u;
                u = pack_bf16x2(sacc[f0][0], sacc[f0][1]); pah[0] = u;
                pal[0] = pack_bf16x2(sacc[f0][0] - __uint_as_float(u << 16),
                                     sacc[f0][1] - __uint_as_float(u & 0xffff0000u));
                u = pack_bf16x2(sacc[f0][2], sacc[f0][3]); pah[1] = u;
                pal[1] = pack_bf16x2(sacc[f0][2] - __uint_as_float(u << 16),
                                     sacc[f0][3] - __uint_as_float(u & 0xffff0000u));
                u = pack_bf16x2(sacc[f1][0], sacc[f1][1]); pah[2] = u;
                pal[2] = pack_bf16x2(sacc[f1][0] - __uint_as_float(u << 16),
                                     sacc[f1][1] - __uint_as_float(u & 0xffff0000u));
                u = pack_bf16x2(sacc[f1][2], sacc[f1][3]); pah[3] = u;
                pal[3] = pack_bf16x2(sacc[f1][2] - __uint_as_float(u << 16),
                                     sacc[f1][3] - __uint_as_float(u & 0xffff0000u));
            }
#pragma unroll
            for (int nb = 0; nb < 4; nb++) {
                uint32_t vh4[4], vl4[4];
                const uint32_t vo = v_base + ks * (16 * APITCH) + nb * 32;
                LDSM_X4T(vh4[0], vh4[1], vh4[2], vh4[3], vo);
                LDSM_X4T(vl4[0], vl4[1], vl4[2], vl4[3], vo + SKV_BYTES);
                MMA_BF16(oacc[nb * 2 + 0], pah, vh4[0], vh4[1]);
                MMA_BF16(oacc[nb * 2 + 0], pah, vl4[0], vl4[1]);
                MMA_BF16(oacc[nb * 2 + 0], pal, vh4[0], vh4[1]);
                MMA_BF16(oacc[nb * 2 + 1], pah, vh4[2], vh4[3]);
                MMA_BF16(oacc[nb * 2 + 1], pah, vl4[2], vl4[3]);
                MMA_BF16(oacc[nb * 2 + 1], pal, vh4[2], vh4[3]);
            }
        }
    }

    // ---- finalize: O = oacc/l, split hi/lo, write g_oh/g_ol ----
    const float inv0 = 1.f / lrow[0];
    const float inv1 = 1.f / lrow[1];
#pragma unroll
    for (int df = 0; df < 8; df++) {
        const int col = h * HSZ + df * 8 + 2 * tig;
        float v00 = oacc[df][0] * inv0, v01 = oacc[df][1] * inv0;
        float v10 = oacc[df][2] * inv1, v11 = oacc[df][3] * inv1;
        uint32_t h0 = pack_bf16x2(v00, v01);
        uint32_t h1 = pack_bf16x2(v10, v11);
        uint32_t l0 = pack_bf16x2(v00 - __uint_as_float(h0 << 16),
                                  v01 - __uint_as_float(h0 & 0xffff0000u));
        uint32_t l1 = pack_bf16x2(v10 - __uint_as_float(h1 << 16),
                                  v11 - __uint_as_float(h1 & 0xffff0000u));
        *(uint32_t*)&g_oh[(rowbase + qr0) * EMB + col] = h0;
        *(uint32_t*)&g_ol[(rowbase + qr0) * EMB + col] = l0;
        *(uint32_t*)&g_oh[(rowbase + qr1) * EMB + col] = h1;
        *(uint32_t*)&g_ol[(rowbase + qr1) * EMB + col] = l1;
    }
}

// ---------------------------------------------------------------------------
extern "C" void kernel_launch(void* const* d_in, const int* in_sizes, int n_in,
                              void* d_out, int out_size)
{
    const float* x     = (const float*)d_in[0];
    const float* W_qkv = (const float*)d_in[1];
    const float* b_qkv = (const float*)d_in[2];
    const float* W_out = (const float*)d_in[3];
    const float* b_out = (const float*)d_in[4];
    float* out = (float*)d_out;

    // 0) weight transpose + split; x split
    prep_wt<0><<<dim3(D3 / 32, EMB / 32), dim3(32, 8)>>>(W_qkv, EMB, D3);
    prep_wt<1><<<dim3(EMB / 32, EMB / 32), dim3(32, 8)>>>(W_out, EMB, EMB);
    prep_split_x<<<ROWS * EMB / 4 / 256, 256>>>(x);

    // 1) QKV projection (HMMA), emits bf16 hi/lo qkv
    cudaFuncSetAttribute(gemm_tc<0>, cudaFuncAttributeMaxDynamicSharedMemorySize, GEMM_SMEM);
    gemm_tc<0><<<dim3(D3 / 128, ROWS / 128), 256, GEMM_SMEM>>>(b_qkv, nullptr);

    // 2) causal flash attention (HMMA), emits bf16 hi/lo O
    cudaFuncSetAttribute(attn_tc, cudaFuncAttributeMaxDynamicSharedMemorySize, ATTN_SMEM);
    attn_tc<<<dim3(SEQ / 128, NH, BATCH), 256, ATTN_SMEM>>>();

    // 3) output projection (HMMA), fp32 out + bias
    cudaFuncSetAttribute(gemm_tc<1>, cudaFuncAttributeMaxDynamicSharedMemorySize, GEMM_SMEM);
    gemm_tc<1><<<dim3(EMB / 128, ROWS / 128), 256, GEMM_SMEM>>>(b_out, out);
}